// round 6
// baseline (speedup 1.0000x reference)
#include <cuda_runtime.h>
#include <cuda_fp16.h>
#include <cstdint>
#include <cstddef>

#define T_TOK 4096
#define DMODEL 1024
#define FDIM 768
#define NEXP 64
#define TOPK 8
#define TK 32768
#define MAXT 320

// ---------------- scratch ----------------
__device__ __align__(16) __half g_Xh[(size_t)T_TOK * DMODEL];
__device__ __align__(16) __half g_Wg[(size_t)NEXP * FDIM * DMODEL];
__device__ __align__(16) __half g_Wu[(size_t)NEXP * FDIM * DMODEL];
__device__ __align__(16) __half g_Wd[(size_t)NEXP * DMODEL * FDIM];
__device__ __align__(16) __half g_H[(size_t)(TK + 128) * FDIM];
__device__ __align__(16) float  g_O2[(size_t)TK * DMODEL];

__device__ int   g_ids[TK];
__device__ float g_w[TK];
__device__ int   g_counts[NEXP];
__device__ int   g_cursor[NEXP];
__device__ int   g_off[NEXP + 1];
__device__ int   g_toff[NEXP + 1];
__device__ int   g_row2tok[TK + 128];
__device__ int   g_slot2row[TK];
__device__ int   g_ntiles[1];

// ---------------- helpers ----------------
__device__ __forceinline__ void mma16816(float* c, const uint32_t* a, const uint32_t* b) {
    asm volatile(
        "mma.sync.aligned.m16n8k16.row.col.f32.f16.f16.f32 "
        "{%0,%1,%2,%3}, {%4,%5,%6,%7}, {%8,%9}, {%0,%1,%2,%3};\n"
        : "+f"(c[0]), "+f"(c[1]), "+f"(c[2]), "+f"(c[3])
        : "r"(a[0]), "r"(a[1]), "r"(a[2]), "r"(a[3]), "r"(b[0]), "r"(b[1]));
}
__device__ __forceinline__ void cp16(void* dst, const void* src) {
    uint32_t d = (uint32_t)__cvta_generic_to_shared(dst);
    asm volatile("cp.async.ca.shared.global [%0], [%1], 16;\n" :: "r"(d), "l"(src));
}
__device__ __forceinline__ void cp_commit() {
    asm volatile("cp.async.commit_group;\n" ::: "memory");
}
__device__ __forceinline__ uint32_t sw128(uint32_t o) { return o ^ ((o >> 3) & 0x70); }

#define LDSM4(r0, r1, r2, r3, addr) \
    asm volatile("ldmatrix.sync.aligned.m8n8.x4.shared.b16 {%0,%1,%2,%3}, [%4];" \
                 : "=r"(r0), "=r"(r1), "=r"(r2), "=r"(r3) : "r"(addr))

// ---------------- small kernels ----------------
__global__ void k_reset() {
    int t = threadIdx.x;
    if (t < NEXP) g_counts[t] = 0;
    if (t < 128) g_row2tok[TK + t] = 0;
}

// one merged convert kernel: [X | Wg | Wu | Wd], 8 fp32->fp16 per thread
__global__ void k_cvt_all(const float* __restrict__ x, const float* __restrict__ wg,
                          const float* __restrict__ wu, const float* __restrict__ wd) {
    const size_t NX = (size_t)T_TOK * DMODEL;
    const size_t NW = (size_t)NEXP * FDIM * DMODEL;
    size_t i = ((size_t)blockIdx.x * blockDim.x + threadIdx.x) * 8;
    const float* s; __half* d;
    if (i < NX)                { s = x  + i;                 d = g_Xh + i; }
    else if (i < NX + NW)      { s = wg + (i - NX);          d = g_Wg + (i - NX); }
    else if (i < NX + 2 * NW)  { s = wu + (i - NX - NW);     d = g_Wu + (i - NX - NW); }
    else if (i < NX + 3 * NW)  { s = wd + (i - NX - 2 * NW); d = g_Wd + (i - NX - 2 * NW); }
    else return;
    float4 v0 = *(const float4*)s;
    float4 v1 = *(const float4*)(s + 4);
    __half2 h0 = __floats2half2_rn(v0.x, v0.y);
    __half2 h1 = __floats2half2_rn(v0.z, v0.w);
    __half2 h2 = __floats2half2_rn(v1.x, v1.y);
    __half2 h3 = __floats2half2_rn(v1.z, v1.w);
    uint4 o;
    o.x = *(uint32_t*)&h0; o.y = *(uint32_t*)&h1;
    o.z = *(uint32_t*)&h2; o.w = *(uint32_t*)&h3;
    *(uint4*)d = o;
}

__global__ void k_router(const float* __restrict__ x, const float* __restrict__ gw) {
    __shared__ float sx[4][DMODEL];
    __shared__ float slog[4][NEXP];
    int t0 = blockIdx.x * 4;
    for (int i = threadIdx.x; i < 4 * DMODEL; i += 256) {
        int tl = i >> 10;
        sx[tl][i & 1023] = x[(size_t)(t0 + tl) * DMODEL + (i & 1023)];
    }
    __syncthreads();
    int tl = threadIdx.x >> 6, e = threadIdx.x & 63;
    const float4* w4 = (const float4*)(gw + (size_t)e * DMODEL);
    const float4* x4 = (const float4*)sx[tl];
    float s = 0.f;
    #pragma unroll 8
    for (int k = 0; k < DMODEL / 4; k++) {
        float4 a = x4[k], b = w4[k];
        s += a.x * b.x + a.y * b.y + a.z * b.z + a.w * b.w;
    }
    slog[tl][e] = s;
    __syncthreads();
    if (threadIdx.x < 4) {
        int t = t0 + threadIdx.x;
        float* lg = slog[threadIdx.x];
        float mx = -1e30f;
        for (int i = 0; i < NEXP; i++) mx = fmaxf(mx, lg[i]);
        float p[NEXP]; float sum = 0.f;
        for (int i = 0; i < NEXP; i++) { p[i] = __expf(lg[i] - mx); sum += p[i]; }
        float inv = 1.f / sum;
        float wsum = 0.f;
        for (int k = 0; k < TOPK; k++) {
            float best = -1.f; int bi = 0;
            for (int i = 0; i < NEXP; i++) if (p[i] > best) { best = p[i]; bi = i; }
            p[bi] = -2.f;
            float wv = best * inv;
            g_w[t * TOPK + k] = wv;
            g_ids[t * TOPK + k] = bi;
            wsum += wv;
            atomicAdd(&g_counts[bi], 1);
        }
        float rn = 1.f / (wsum + 1e-20f);
        for (int k = 0; k < TOPK; k++) g_w[t * TOPK + k] *= rn;
    }
}

__global__ void k_scan() {
    if (threadIdx.x < NEXP) g_cursor[threadIdx.x] = 0;
    if (threadIdx.x == 0) {
        int off = 0, toff = 0;
        for (int e = 0; e < NEXP; e++) {
            g_off[e] = off; g_toff[e] = toff;
            off += g_counts[e];
            toff += (g_counts[e] + 127) >> 7;
        }
        g_off[NEXP] = off; g_toff[NEXP] = toff;
        g_ntiles[0] = toff;
    }
}

__global__ void k_scatter() {
    int i = blockIdx.x * 256 + threadIdx.x;
    if (i >= TK) return;
    int e = g_ids[i];
    int p = g_off[e] + atomicAdd(&g_cursor[e], 1);
    g_row2tok[p] = i >> 3;
    g_slot2row[i] = p;
}

// ---------------- GEMM1 + SwiGLU: 4-stage, prefetch distance 3 ----------------
#define STAGES 4
#define STG1 32768

__global__ __launch_bounds__(256) void k_gemm1() {
    extern __shared__ char smem[];
    uint32_t sb = (uint32_t)__cvta_generic_to_shared(smem);
    int tid = threadIdx.x;
    int by = blockIdx.y;
    if (by >= g_ntiles[0]) return;

    __shared__ int s_e, s_m0, s_valid;
    __shared__ int stok[128];
    if (tid == 0) {
        int e = 0;
        while (!(by >= g_toff[e] && by < g_toff[e + 1])) e++;
        int lt = by - g_toff[e];
        s_e = e;
        s_m0 = g_off[e] + lt * 128;
        s_valid = min(128, (g_off[e + 1] - g_off[e]) - lt * 128);
    }
    __syncthreads();
    int e = s_e, m0 = s_m0;
    if (tid < 128) stok[tid] = g_row2tok[m0 + tid];
    __syncthreads();

    int f0 = blockIdx.x * 64;
    int arow = tid >> 1;
    int cb = (tid & 1) * 64;
    const __half* asrc = g_Xh + (size_t)stok[arow] * DMODEL + (cb >> 1);
    int wh = tid >> 7;
    int wrow = (tid & 127) >> 1;
    const __half* wsrc = (wh ? g_Wu : g_Wg) + ((size_t)e * FDIM + f0 + wrow) * DMODEL + (cb >> 1);
    uint32_t a_off = (uint32_t)arow * 128 + cb;
    uint32_t w_off = 16384 + (uint32_t)wh * 8192 + (uint32_t)wrow * 128 + cb;

    int warp = tid >> 5, lane = tid & 31;
    int wm = warp >> 1, wn = warp & 1;
    int grp = lane >> 2, tig = lane & 3;

    uint32_t aRow = (uint32_t)(lane & 15);
    uint32_t aKb  = (uint32_t)(lane >> 4) * 16;
    uint32_t bRow = (uint32_t)((lane & 7) + ((lane >> 4) * 8));
    uint32_t bKb  = (uint32_t)((lane >> 3) & 1) * 16;

    float accg[2][4][4], accu[2][4][4];
    #pragma unroll
    for (int a = 0; a < 2; a++)
        #pragma unroll
        for (int b = 0; b < 4; b++)
            #pragma unroll
            for (int c = 0; c < 4; c++) { accg[a][b][c] = 0.f; accu[a][b][c] = 0.f; }

    const int KS = DMODEL / 64;   // 16
    char* tiles = smem;

    // prologue: chunks 0,1,2
    #pragma unroll
    for (int p = 0; p < 3; p++) {
        char* st = tiles + p * STG1;
        const __half* a_s = asrc + p * 64;
        const __half* w_s = wsrc + p * 64;
        #pragma unroll
        for (int j = 0; j < 4; j++) cp16(st + sw128(a_off + j * 16), a_s + j * 8);
        #pragma unroll
        for (int j = 0; j < 4; j++) cp16(st + sw128(w_off + j * 16), w_s + j * 8);
        cp_commit();
    }

    for (int ks = 0; ks < KS; ks++) {
        if (ks < KS - 2)      { asm volatile("cp.async.wait_group 2;\n" ::: "memory"); }
        else if (ks == KS - 2){ asm volatile("cp.async.wait_group 1;\n" ::: "memory"); }
        else                  { asm volatile("cp.async.wait_group 0;\n" ::: "memory"); }
        __syncthreads();
        if (ks + 3 < KS) {
            char* st = tiles + ((ks + 3) & 3) * STG1;
            const __half* a_s = asrc + (ks + 3) * 64;
            const __half* w_s = wsrc + (ks + 3) * 64;
            #pragma unroll
            for (int j = 0; j < 4; j++) cp16(st + sw128(a_off + j * 16), a_s + j * 8);
            #pragma unroll
            for (int j = 0; j < 4; j++) cp16(st + sw128(w_off + j * 16), w_s + j * 8);
            cp_commit();
        }
        uint32_t stg = sb + (ks & 3) * STG1;
        #pragma unroll
        for (int kk = 0; kk < 4; kk++) {
            uint32_t a[2][4];
            #pragma unroll
            for (int mi = 0; mi < 2; mi++) {
                uint32_t off = (uint32_t)(wm * 32 + mi * 16 + aRow) * 128 + kk * 32 + aKb;
                LDSM4(a[mi][0], a[mi][1], a[mi][2], a[mi][3], stg + sw128(off));
            }
            uint32_t bg[4][2], bu[4][2];
            #pragma unroll
            for (int h = 0; h < 2; h++) {
                uint32_t off = 16384 + (uint32_t)(wn * 32 + h * 16 + bRow) * 128 + kk * 32 + bKb;
                LDSM4(bg[h * 2][0], bg[h * 2][1], bg[h * 2 + 1][0], bg[h * 2 + 1][1], stg + sw128(off));
                uint32_t offu = off + 8192;
                LDSM4(bu[h * 2][0], bu[h * 2][1], bu[h * 2 + 1][0], bu[h * 2 + 1][1], stg + sw128(offu));
            }
            #pragma unroll
            for (int mi = 0; mi < 2; mi++)
                #pragma unroll
                for (int ng = 0; ng < 4; ng++) {
                    mma16816(accg[mi][ng], a[mi], bg[ng]);
                    mma16816(accu[mi][ng], a[mi], bu[ng]);
                }
        }
    }

    int valid = s_valid;
    #pragma unroll
    for (int mi = 0; mi < 2; mi++)
        #pragma unroll
        for (int ng = 0; ng < 4; ng++) {
            int rbase = wm * 32 + mi * 16 + grp;
            int col = wn * 32 + ng * 8 + tig * 2;
            #pragma unroll
            for (int h = 0; h < 2; h++) {
                int r = rbase + h * 8;
                if (r < valid) {
                    float g0 = accg[mi][ng][h * 2 + 0], g1 = accg[mi][ng][h * 2 + 1];
                    float u0 = accu[mi][ng][h * 2 + 0], u1 = accu[mi][ng][h * 2 + 1];
                    float h0 = g0 / (1.f + __expf(-g0)) * u0;
                    float h1 = g1 / (1.f + __expf(-g1)) * u1;
                    *(__half2*)&g_H[(size_t)(m0 + r) * FDIM + f0 + col] = __floats2half2_rn(h0, h1);
                }
            }
        }
}

// ---------------- GEMM2: 4-stage, prefetch distance 3 ----------------
#define STG2 32768

__global__ __launch_bounds__(256) void k_gemm2() {
    extern __shared__ char smem[];
    uint32_t sb = (uint32_t)__cvta_generic_to_shared(smem);
    int tid = threadIdx.x;
    int by = blockIdx.y;
    if (by >= g_ntiles[0]) return;

    __shared__ int s_e, s_m0, s_valid;
    if (tid == 0) {
        int e = 0;
        while (!(by >= g_toff[e] && by < g_toff[e + 1])) e++;
        int lt = by - g_toff[e];
        s_e = e;
        s_m0 = g_off[e] + lt * 128;
        s_valid = min(128, (g_off[e + 1] - g_off[e]) - lt * 128);
    }
    __syncthreads();
    int e = s_e, m0 = s_m0;
    int n0 = blockIdx.x * 128;

    int row = tid >> 1;
    int cb = (tid & 1) * 64;
    const __half* asrc = g_H + (size_t)(m0 + row) * FDIM + (cb >> 1);
    const __half* bsrc = g_Wd + ((size_t)e * DMODEL + n0 + row) * FDIM + (cb >> 1);
    uint32_t a_off = (uint32_t)row * 128 + cb;
    uint32_t b_off = 16384 + a_off;

    int warp = tid >> 5, lane = tid & 31;
    int wm = warp >> 1, wn = warp & 1;
    int grp = lane >> 2, tig = lane & 3;

    uint32_t aRow = (uint32_t)(lane & 15);
    uint32_t aKb  = (uint32_t)(lane >> 4) * 16;
    uint32_t bRow = (uint32_t)((lane & 7) + ((lane >> 4) * 8));
    uint32_t bKb  = (uint32_t)((lane >> 3) & 1) * 16;

    float acc[2][8][4];
    #pragma unroll
    for (int a = 0; a < 2; a++)
        #pragma unroll
        for (int b = 0; b < 8; b++)
            #pragma unroll
            for (int c = 0; c < 4; c++) acc[a][b][c] = 0.f;

    const int KS = FDIM / 64;     // 12
    char* tiles = smem;

    #pragma unroll
    for (int p = 0; p < 3; p++) {
        char* st = tiles + p * STG2;
        const __half* a_s = asrc + p * 64;
        const __half* b_s = bsrc + p * 64;
        #pragma unroll
        for (int j = 0; j < 4; j++) cp16(st + sw128(a_off + j * 16), a_s + j * 8);
        #pragma unroll
        for (int j = 0; j < 4; j++) cp16(st + sw128(b_off + j * 16), b_s + j * 8);
        cp_commit();
    }

    for (int ks = 0; ks < KS; ks++) {
        if (ks < KS - 2)      { asm volatile("cp.async.wait_group 2;\n" ::: "memory"); }
        else if (ks == KS - 2){ asm volatile("cp.async.wait_group 1;\n" ::: "memory"); }
        else                  { asm volatile("cp.async.wait_group 0;\n" ::: "memory"); }
        __syncthreads();
        if (ks + 3 < KS) {
            char* st = tiles + ((ks + 3) & 3) * STG2;
            const __half* a_s = asrc + (ks + 3) * 64;
            const __half* b_s = bsrc + (ks + 3) * 64;
            #pragma unroll
            for (int j = 0; j < 4; j++) cp16(st + sw128(a_off + j * 16), a_s + j * 8);
            #pragma unroll
            for (int j = 0; j < 4; j++) cp16(st + sw128(b_off + j * 16), b_s + j * 8);
            cp_commit();
        }
        uint32_t stg = sb + (ks & 3) * STG2;
        #pragma unroll
        for (int kk = 0; kk < 4; kk++) {
            uint32_t a[2][4];
            #pragma unroll
            for (int mi = 0; mi < 2; mi++) {
                uint32_t off = (uint32_t)(wm * 32 + mi * 16 + aRow) * 128 + kk * 32 + aKb;
                LDSM4(a[mi][0], a[mi][1], a[mi][2], a[mi][3], stg + sw128(off));
            }
            uint32_t b[8][2];
            #pragma unroll
            for (int h = 0; h < 4; h++) {
                uint32_t off = 16384 + (uint32_t)(wn * 64 + h * 16 + bRow) * 128 + kk * 32 + bKb;
                LDSM4(b[h * 2][0], b[h * 2][1], b[h * 2 + 1][0], b[h * 2 + 1][1], stg + sw128(off));
            }
            #pragma unroll
            for (int mi = 0; mi < 2; mi++)
                #pragma unroll
                for (int ng = 0; ng < 8; ng++)
                    mma16816(acc[mi][ng], a[mi], b[ng]);
        }
    }

    int valid = s_valid;
    #pragma unroll
    for (int mi = 0; mi < 2; mi++)
        #pragma unroll
        for (int ng = 0; ng < 8; ng++) {
            int rbase = wm * 32 + mi * 16 + grp;
            int col = wn * 64 + ng * 8 + tig * 2;
            #pragma unroll
            for (int h = 0; h < 2; h++) {
                int r = rbase + h * 8;
                if (r < valid) {
                    float2 v = make_float2(acc[mi][ng][h * 2 + 0], acc[mi][ng][h * 2 + 1]);
                    *(float2*)&g_O2[(size_t)(m0 + r) * DMODEL + n0 + col] = v;
                }
            }
        }
}

__global__ void k_comb(float* __restrict__ y) {
    int i = blockIdx.x * 256 + threadIdx.x;
    int t = i >> 8;
    int d4 = (i & 255) * 4;
    float4 acc = make_float4(0.f, 0.f, 0.f, 0.f);
    #pragma unroll
    for (int k = 0; k < TOPK; k++) {
        float w = g_w[t * TOPK + k];
        int r = g_slot2row[t * TOPK + k];
        float4 v = *(const float4*)&g_O2[(size_t)r * DMODEL + d4];
        acc.x += w * v.x; acc.y += w * v.y; acc.z += w * v.z; acc.w += w * v.w;
    }
    *(float4*)(y + (size_t)t * DMODEL + d4) = acc;
}

// ---------------- launch ----------------
extern "C" void kernel_launch(void* const* d_in, const int* in_sizes, int n_in,
                              void* d_out, int out_size) {
    const float* x  = (const float*)d_in[0];
    const float* gw = (const float*)d_in[1];
    const float* wg = (const float*)d_in[2];
    const float* wu = (const float*)d_in[3];
    const float* wd = (const float*)d_in[4];
    float* y = (float*)d_out;

    const int SMEM = STAGES * 32768;   // 131072
    cudaFuncSetAttribute(k_gemm1, cudaFuncAttributeMaxDynamicSharedMemorySize, SMEM);
    cudaFuncSetAttribute(k_gemm2, cudaFuncAttributeMaxDynamicSharedMemorySize, SMEM);

    // order: gemm1 is launch index 5 (ncu -s 5 -c 1 profiles it)
    k_reset<<<1, 128>>>();                                            // 0
    k_router<<<T_TOK / 4, 256>>>(x, gw);                              // 1
    k_scan<<<1, 64>>>();                                              // 2
    k_scatter<<<TK / 256, 256>>>();                                   // 3
    {
        size_t total = (size_t)T_TOK * DMODEL + 3ull * NEXP * FDIM * DMODEL;
        k_cvt_all<<<(unsigned)(total / 2048), 256>>>(x, wg, wu, wd);  // 4
    }
    k_gemm1<<<dim3(FDIM / 64, MAXT), 256, SMEM>>>();                  // 5
    k_gemm2<<<dim3(DMODEL / 128, MAXT), 256, SMEM>>>();               // 6
    k_comb<<<(T_TOK * DMODEL / 4) / 256, 256>>>(y);                   // 7
}

// round 7
// speedup vs baseline: 1.1178x; 1.1178x over previous
#include <cuda_runtime.h>
#include <cuda_fp16.h>
#include <cstdint>
#include <cstddef>

#define T_TOK 4096
#define DMODEL 1024
#define FDIM 768
#define NEXP 64
#define TOPK 8
#define TK 32768
#define MAXT 320

// ---------------- scratch ----------------
__device__ __align__(16) __half g_Xh[(size_t)T_TOK * DMODEL];
__device__ __align__(16) __half g_Wg[(size_t)NEXP * FDIM * DMODEL];
__device__ __align__(16) __half g_Wu[(size_t)NEXP * FDIM * DMODEL];
__device__ __align__(16) __half g_Wd[(size_t)NEXP * DMODEL * FDIM];
__device__ __align__(16) __half g_H[(size_t)(TK + 128) * FDIM];
__device__ __align__(16) float  g_O2[(size_t)TK * DMODEL];

__device__ int   g_ids[TK];
__device__ float g_w[TK];
__device__ int   g_counts[NEXP];
__device__ int   g_cursor[NEXP];
__device__ int   g_off[NEXP + 1];
__device__ int   g_toff[NEXP + 1];
__device__ int   g_row2tok[TK + 128];
__device__ int   g_slot2row[TK];
__device__ int   g_ntiles[1];

// ---------------- helpers ----------------
__device__ __forceinline__ void mma16816(float* c, const uint32_t* a, const uint32_t* b) {
    asm volatile(
        "mma.sync.aligned.m16n8k16.row.col.f32.f16.f16.f32 "
        "{%0,%1,%2,%3}, {%4,%5,%6,%7}, {%8,%9}, {%0,%1,%2,%3};\n"
        : "+f"(c[0]), "+f"(c[1]), "+f"(c[2]), "+f"(c[3])
        : "r"(a[0]), "r"(a[1]), "r"(a[2]), "r"(a[3]), "r"(b[0]), "r"(b[1]));
}
__device__ __forceinline__ void cp16(void* dst, const void* src) {
    uint32_t d = (uint32_t)__cvta_generic_to_shared(dst);
    asm volatile("cp.async.ca.shared.global [%0], [%1], 16;\n" :: "r"(d), "l"(src));
}
__device__ __forceinline__ void cp_commit() {
    asm volatile("cp.async.commit_group;\n" ::: "memory");
}
__device__ __forceinline__ uint32_t sw128(uint32_t o) { return o ^ ((o >> 3) & 0x70); }

#define LDSM4(r0, r1, r2, r3, addr) \
    asm volatile("ldmatrix.sync.aligned.m8n8.x4.shared.b16 {%0,%1,%2,%3}, [%4];" \
                 : "=r"(r0), "=r"(r1), "=r"(r2), "=r"(r3) : "r"(addr))

// ---------------- launch 1: convert (+reset embedded) ----------------
__global__ void k_cvt_all(const float* __restrict__ x, const float* __restrict__ wg,
                          const float* __restrict__ wu, const float* __restrict__ wd) {
    if (blockIdx.x == 0) {
        int t = threadIdx.x;
        if (t < NEXP) g_counts[t] = 0;
        if (t < 128) g_row2tok[TK + t] = 0;
    }
    const size_t NX = (size_t)T_TOK * DMODEL;
    const size_t NW = (size_t)NEXP * FDIM * DMODEL;
    size_t i = ((size_t)blockIdx.x * blockDim.x + threadIdx.x) * 8;
    const float* s; __half* d;
    if (i < NX)                { s = x  + i;                 d = g_Xh + i; }
    else if (i < NX + NW)      { s = wg + (i - NX);          d = g_Wg + (i - NX); }
    else if (i < NX + 2 * NW)  { s = wu + (i - NX - NW);     d = g_Wu + (i - NX - NW); }
    else if (i < NX + 3 * NW)  { s = wd + (i - NX - 2 * NW); d = g_Wd + (i - NX - 2 * NW); }
    else return;
    float4 v0 = *(const float4*)s;
    float4 v1 = *(const float4*)(s + 4);
    __half2 h0 = __floats2half2_rn(v0.x, v0.y);
    __half2 h1 = __floats2half2_rn(v0.z, v0.w);
    __half2 h2 = __floats2half2_rn(v1.x, v1.y);
    __half2 h3 = __floats2half2_rn(v1.z, v1.w);
    uint4 o;
    o.x = *(uint32_t*)&h0; o.y = *(uint32_t*)&h1;
    o.z = *(uint32_t*)&h2; o.w = *(uint32_t*)&h3;
    *(uint4*)d = o;
}

// ---------------- launch 2: router ----------------
__global__ void k_router(const float* __restrict__ x, const float* __restrict__ gw) {
    __shared__ float sx[4][DMODEL];
    __shared__ float slog[4][NEXP];
    int t0 = blockIdx.x * 4;
    for (int i = threadIdx.x; i < 4 * DMODEL; i += 256) {
        int tl = i >> 10;
        sx[tl][i & 1023] = x[(size_t)(t0 + tl) * DMODEL + (i & 1023)];
    }
    __syncthreads();
    int tl = threadIdx.x >> 6, e = threadIdx.x & 63;
    const float4* w4 = (const float4*)(gw + (size_t)e * DMODEL);
    const float4* x4 = (const float4*)sx[tl];
    float s = 0.f;
    #pragma unroll 8
    for (int k = 0; k < DMODEL / 4; k++) {
        float4 a = x4[k], b = w4[k];
        s += a.x * b.x + a.y * b.y + a.z * b.z + a.w * b.w;
    }
    slog[tl][e] = s;
    __syncthreads();
    if (threadIdx.x < 4) {
        int t = t0 + threadIdx.x;
        float* lg = slog[threadIdx.x];
        float mx = -1e30f;
        for (int i = 0; i < NEXP; i++) mx = fmaxf(mx, lg[i]);
        float p[NEXP]; float sum = 0.f;
        for (int i = 0; i < NEXP; i++) { p[i] = __expf(lg[i] - mx); sum += p[i]; }
        float inv = 1.f / sum;
        float wsum = 0.f;
        for (int k = 0; k < TOPK; k++) {
            float best = -1.f; int bi = 0;
            for (int i = 0; i < NEXP; i++) if (p[i] > best) { best = p[i]; bi = i; }
            p[bi] = -2.f;
            float wv = best * inv;
            g_w[t * TOPK + k] = wv;
            g_ids[t * TOPK + k] = bi;
            wsum += wv;
            atomicAdd(&g_counts[bi], 1);
        }
        float rn = 1.f / (wsum + 1e-20f);
        for (int k = 0; k < TOPK; k++) g_w[t * TOPK + k] *= rn;
    }
}

// ---------------- launch 3: scan + scatter (single block) ----------------
__global__ void k_scan_scatter() {
    int tid = threadIdx.x;
    if (tid < NEXP) g_cursor[tid] = 0;
    if (tid == 0) {
        int off = 0, toff = 0;
        for (int e = 0; e < NEXP; e++) {
            g_off[e] = off; g_toff[e] = toff;
            off += g_counts[e];
            toff += (g_counts[e] + 127) >> 7;
        }
        g_off[NEXP] = off; g_toff[NEXP] = toff;
        g_ntiles[0] = toff;
    }
    __syncthreads();
    for (int i = tid; i < TK; i += 1024) {
        int e = g_ids[i];
        int p = g_off[e] + atomicAdd(&g_cursor[e], 1);
        g_row2tok[p] = i >> 3;
        g_slot2row[i] = p;
    }
}

// ---------------- launch 4: GEMM1 + SwiGLU (2-stage, 2 CTAs/SM) ----------------
#define STG1 32768

__global__ __launch_bounds__(256, 2) void k_gemm1() {
    extern __shared__ char smem[];
    uint32_t sb = (uint32_t)__cvta_generic_to_shared(smem);
    int tid = threadIdx.x;
    int by = blockIdx.y;
    if (by >= g_ntiles[0]) return;

    __shared__ int s_e, s_m0, s_valid;
    __shared__ int stok[128];
    if (tid == 0) {
        int e = 0;
        while (!(by >= g_toff[e] && by < g_toff[e + 1])) e++;
        int lt = by - g_toff[e];
        s_e = e;
        s_m0 = g_off[e] + lt * 128;
        s_valid = min(128, (g_off[e + 1] - g_off[e]) - lt * 128);
    }
    __syncthreads();
    int e = s_e, m0 = s_m0;
    if (tid < 128) stok[tid] = g_row2tok[m0 + tid];
    __syncthreads();

    int f0 = blockIdx.x * 64;
    int arow = tid >> 1;
    int cb = (tid & 1) * 64;
    const __half* asrc = g_Xh + (size_t)stok[arow] * DMODEL + (cb >> 1);
    int wh = tid >> 7;
    int wrow = (tid & 127) >> 1;
    const __half* wsrc = (wh ? g_Wu : g_Wg) + ((size_t)e * FDIM + f0 + wrow) * DMODEL + (cb >> 1);
    uint32_t a_off = (uint32_t)arow * 128 + cb;
    uint32_t w_off = 16384 + (uint32_t)wh * 8192 + (uint32_t)wrow * 128 + cb;

    int warp = tid >> 5, lane = tid & 31;
    int wm = warp >> 1, wn = warp & 1;
    int grp = lane >> 2, tig = lane & 3;

    uint32_t aRow = (uint32_t)(lane & 15);
    uint32_t aKb  = (uint32_t)(lane >> 4) * 16;
    uint32_t bRow = (uint32_t)((lane & 7) + ((lane >> 4) * 8));
    uint32_t bKb  = (uint32_t)((lane >> 3) & 1) * 16;

    float accg[2][4][4], accu[2][4][4];
    #pragma unroll
    for (int a = 0; a < 2; a++)
        #pragma unroll
        for (int b = 0; b < 4; b++)
            #pragma unroll
            for (int c = 0; c < 4; c++) { accg[a][b][c] = 0.f; accu[a][b][c] = 0.f; }

    const int KS = DMODEL / 64;   // 16
    char* tiles = smem;

    // prologue: chunk 0
    {
        #pragma unroll
        for (int j = 0; j < 4; j++) cp16(tiles + sw128(a_off + j * 16), asrc + j * 8);
        #pragma unroll
        for (int j = 0; j < 4; j++) cp16(tiles + sw128(w_off + j * 16), wsrc + j * 8);
        cp_commit();
    }

    for (int ks = 0; ks < KS; ks++) {
        if (ks + 1 < KS) {
            char* st = tiles + ((ks + 1) & 1) * STG1;
            const __half* a_s = asrc + (ks + 1) * 64;
            const __half* w_s = wsrc + (ks + 1) * 64;
            #pragma unroll
            for (int j = 0; j < 4; j++) cp16(st + sw128(a_off + j * 16), a_s + j * 8);
            #pragma unroll
            for (int j = 0; j < 4; j++) cp16(st + sw128(w_off + j * 16), w_s + j * 8);
            cp_commit();
            asm volatile("cp.async.wait_group 1;\n" ::: "memory");
        } else {
            asm volatile("cp.async.wait_group 0;\n" ::: "memory");
        }
        __syncthreads();
        uint32_t stg = sb + (ks & 1) * STG1;
        #pragma unroll
        for (int kk = 0; kk < 4; kk++) {
            uint32_t a[2][4];
            #pragma unroll
            for (int mi = 0; mi < 2; mi++) {
                uint32_t off = (uint32_t)(wm * 32 + mi * 16 + aRow) * 128 + kk * 32 + aKb;
                LDSM4(a[mi][0], a[mi][1], a[mi][2], a[mi][3], stg + sw128(off));
            }
            uint32_t bg[4][2], bu[4][2];
            #pragma unroll
            for (int h = 0; h < 2; h++) {
                uint32_t off = 16384 + (uint32_t)(wn * 32 + h * 16 + bRow) * 128 + kk * 32 + bKb;
                LDSM4(bg[h * 2][0], bg[h * 2][1], bg[h * 2 + 1][0], bg[h * 2 + 1][1], stg + sw128(off));
                uint32_t offu = off + 8192;
                LDSM4(bu[h * 2][0], bu[h * 2][1], bu[h * 2 + 1][0], bu[h * 2 + 1][1], stg + sw128(offu));
            }
            #pragma unroll
            for (int mi = 0; mi < 2; mi++)
                #pragma unroll
                for (int ng = 0; ng < 4; ng++) {
                    mma16816(accg[mi][ng], a[mi], bg[ng]);
                    mma16816(accu[mi][ng], a[mi], bu[ng]);
                }
        }
        __syncthreads();
    }

    int valid = s_valid;
    #pragma unroll
    for (int mi = 0; mi < 2; mi++)
        #pragma unroll
        for (int ng = 0; ng < 4; ng++) {
            int rbase = wm * 32 + mi * 16 + grp;
            int col = wn * 32 + ng * 8 + tig * 2;
            #pragma unroll
            for (int h = 0; h < 2; h++) {
                int r = rbase + h * 8;
                if (r < valid) {
                    float g0 = accg[mi][ng][h * 2 + 0], g1 = accg[mi][ng][h * 2 + 1];
                    float u0 = accu[mi][ng][h * 2 + 0], u1 = accu[mi][ng][h * 2 + 1];
                    float h0 = g0 / (1.f + __expf(-g0)) * u0;
                    float h1 = g1 / (1.f + __expf(-g1)) * u1;
                    *(__half2*)&g_H[(size_t)(m0 + r) * FDIM + f0 + col] = __floats2half2_rn(h0, h1);
                }
            }
        }
}

// ---------------- launch 5: GEMM2 (2-stage, 2 CTAs/SM) ----------------
#define STG2 32768

__global__ __launch_bounds__(256, 2) void k_gemm2() {
    extern __shared__ char smem[];
    uint32_t sb = (uint32_t)__cvta_generic_to_shared(smem);
    int tid = threadIdx.x;
    int by = blockIdx.y;
    if (by >= g_ntiles[0]) return;

    __shared__ int s_e, s_m0, s_valid;
    if (tid == 0) {
        int e = 0;
        while (!(by >= g_toff[e] && by < g_toff[e + 1])) e++;
        int lt = by - g_toff[e];
        s_e = e;
        s_m0 = g_off[e] + lt * 128;
        s_valid = min(128, (g_off[e + 1] - g_off[e]) - lt * 128);
    }
    __syncthreads();
    int e = s_e, m0 = s_m0;
    int n0 = blockIdx.x * 128;

    int row = tid >> 1;
    int cb = (tid & 1) * 64;
    const __half* asrc = g_H + (size_t)(m0 + row) * FDIM + (cb >> 1);
    const __half* bsrc = g_Wd + ((size_t)e * DMODEL + n0 + row) * FDIM + (cb >> 1);
    uint32_t a_off = (uint32_t)row * 128 + cb;
    uint32_t b_off = 16384 + a_off;

    int warp = tid >> 5, lane = tid & 31;
    int wm = warp >> 1, wn = warp & 1;
    int grp = lane >> 2, tig = lane & 3;

    uint32_t aRow = (uint32_t)(lane & 15);
    uint32_t aKb  = (uint32_t)(lane >> 4) * 16;
    uint32_t bRow = (uint32_t)((lane & 7) + ((lane >> 4) * 8));
    uint32_t bKb  = (uint32_t)((lane >> 3) & 1) * 16;

    float acc[2][8][4];
    #pragma unroll
    for (int a = 0; a < 2; a++)
        #pragma unroll
        for (int b = 0; b < 8; b++)
            #pragma unroll
            for (int c = 0; c < 4; c++) acc[a][b][c] = 0.f;

    const int KS = FDIM / 64;     // 12
    char* tiles = smem;

    {
        #pragma unroll
        for (int j = 0; j < 4; j++) cp16(tiles + sw128(a_off + j * 16), asrc + j * 8);
        #pragma unroll
        for (int j = 0; j < 4; j++) cp16(tiles + sw128(b_off + j * 16), bsrc + j * 8);
        cp_commit();
    }

    for (int ks = 0; ks < KS; ks++) {
        if (ks + 1 < KS) {
            char* st = tiles + ((ks + 1) & 1) * STG2;
            const __half* a_s = asrc + (ks + 1) * 64;
            const __half* b_s = bsrc + (ks + 1) * 64;
            #pragma unroll
            for (int j = 0; j < 4; j++) cp16(st + sw128(a_off + j * 16), a_s + j * 8);
            #pragma unroll
            for (int j = 0; j < 4; j++) cp16(st + sw128(b_off + j * 16), b_s + j * 8);
            cp_commit();
            asm volatile("cp.async.wait_group 1;\n" ::: "memory");
        } else {
            asm volatile("cp.async.wait_group 0;\n" ::: "memory");
        }
        __syncthreads();
        uint32_t stg = sb + (ks & 1) * STG2;
        #pragma unroll
        for (int kk = 0; kk < 4; kk++) {
            uint32_t a[2][4];
            #pragma unroll
            for (int mi = 0; mi < 2; mi++) {
                uint32_t off = (uint32_t)(wm * 32 + mi * 16 + aRow) * 128 + kk * 32 + aKb;
                LDSM4(a[mi][0], a[mi][1], a[mi][2], a[mi][3], stg + sw128(off));
            }
            uint32_t b[8][2];
            #pragma unroll
            for (int h = 0; h < 4; h++) {
                uint32_t off = 16384 + (uint32_t)(wn * 64 + h * 16 + bRow) * 128 + kk * 32 + bKb;
                LDSM4(b[h * 2][0], b[h * 2][1], b[h * 2 + 1][0], b[h * 2 + 1][1], stg + sw128(off));
            }
            #pragma unroll
            for (int mi = 0; mi < 2; mi++)
                #pragma unroll
                for (int ng = 0; ng < 8; ng++)
                    mma16816(acc[mi][ng], a[mi], b[ng]);
        }
        __syncthreads();
    }

    int valid = s_valid;
    #pragma unroll
    for (int mi = 0; mi < 2; mi++)
        #pragma unroll
        for (int ng = 0; ng < 8; ng++) {
            int rbase = wm * 32 + mi * 16 + grp;
            int col = wn * 64 + ng * 8 + tig * 2;
            #pragma unroll
            for (int h = 0; h < 2; h++) {
                int r = rbase + h * 8;
                if (r < valid) {
                    float2 v = make_float2(acc[mi][ng][h * 2 + 0], acc[mi][ng][h * 2 + 1]);
                    *(float2*)&g_O2[(size_t)(m0 + r) * DMODEL + n0 + col] = v;
                }
            }
        }
}

// ---------------- launch 6: combine ----------------
__global__ void k_comb(float* __restrict__ y) {
    int i = blockIdx.x * 256 + threadIdx.x;
    int t = i >> 8;
    int d4 = (i & 255) * 4;
    float4 acc = make_float4(0.f, 0.f, 0.f, 0.f);
    #pragma unroll
    for (int k = 0; k < TOPK; k++) {
        float w = g_w[t * TOPK + k];
        int r = g_slot2row[t * TOPK + k];
        float4 v = *(const float4*)&g_O2[(size_t)r * DMODEL + d4];
        acc.x += w * v.x; acc.y += w * v.y; acc.z += w * v.z; acc.w += w * v.w;
    }
    *(float4*)(y + (size_t)t * DMODEL + d4) = acc;
}

// ---------------- launch ----------------
extern "C" void kernel_launch(void* const* d_in, const int* in_sizes, int n_in,
                              void* d_out, int out_size) {
    const float* x  = (const float*)d_in[0];
    const float* gw = (const float*)d_in[1];
    const float* wg = (const float*)d_in[2];
    const float* wu = (const float*)d_in[3];
    const float* wd = (const float*)d_in[4];
    float* y = (float*)d_out;

    cudaFuncSetAttribute(k_gemm1, cudaFuncAttributeMaxDynamicSharedMemorySize, 2 * STG1);
    cudaFuncSetAttribute(k_gemm2, cudaFuncAttributeMaxDynamicSharedMemorySize, 2 * STG2);

    {
        size_t total = (size_t)T_TOK * DMODEL + 3ull * NEXP * FDIM * DMODEL;
        k_cvt_all<<<(unsigned)(total / 2048), 256>>>(x, wg, wu, wd);  // launch 1
    }
    k_router<<<T_TOK / 4, 256>>>(x, gw);                              // launch 2
    k_scan_scatter<<<1, 1024>>>();                                    // launch 3
    k_gemm1<<<dim3(FDIM / 64, MAXT), 256, 2 * STG1>>>();              // launch 4 (= process #6 for ncu)
    k_gemm2<<<dim3(DMODEL / 128, MAXT), 256, 2 * STG2>>>();           // launch 5
    k_comb<<<(T_TOK * DMODEL / 4) / 256, 256>>>(y);                   // launch 6
}